// round 12
// baseline (speedup 1.0000x reference)
#include <cuda_runtime.h>
#include <cuda_bf16.h>
#include <cstdint>

#define Bsz 4096
#define Tst 128
#define NL  256
#define NSt 64
#define NOt 32
#define Vt  64
#define MT  16
#define THR 256
#define XR  264        // x row stride (bf16)
#define NCH 16
#define SLG 36

typedef uint32_t u32;

__device__ __nv_bfloat16 g_w1h[(size_t)NSt * NL * NL];
__device__ __nv_bfloat16 g_w1l[(size_t)NSt * NL * NL];
__device__ __nv_bfloat16 g_w2h[(size_t)NSt * NOt * NL];
__device__ __nv_bfloat16 g_w2l[(size_t)NSt * NOt * NL];

__device__ __forceinline__ u32 s2u(const void* p) {
    return (u32)__cvta_generic_to_shared(p);
}
__device__ __forceinline__ void ldsm4(u32* r, u32 a) {
    asm volatile("ldmatrix.sync.aligned.m8n8.x4.shared.b16 {%0,%1,%2,%3}, [%4];"
        : "=r"(r[0]), "=r"(r[1]), "=r"(r[2]), "=r"(r[3]) : "r"(a));
}
__device__ __forceinline__ void mma16(float* c, const u32* a, u32 b0, u32 b1) {
    asm volatile("mma.sync.aligned.m16n8k16.row.col.f32.bf16.bf16.f32 "
        "{%0,%1,%2,%3},{%4,%5,%6,%7},{%8,%9},{%0,%1,%2,%3};"
        : "+f"(c[0]), "+f"(c[1]), "+f"(c[2]), "+f"(c[3])
        : "r"(a[0]), "r"(a[1]), "r"(a[2]), "r"(a[3]), "r"(b0), "r"(b1));
}
__device__ __forceinline__ void cpa16(u32 dst, const void* src) {
    asm volatile("cp.async.cg.shared.global [%0], [%1], 16;"
        :: "r"(dst), "l"(src) : "memory");
}
#define CPA_COMMIT() asm volatile("cp.async.commit_group;" ::: "memory")
#define CPA_WAIT1()  asm volatile("cp.async.wait_group 1;" ::: "memory")

// Fast branch-free tanh: |abs err| <~ 2^-21, no overflow.
__device__ __forceinline__ float ftanh(float x) {
    float t = __expf(-2.f * fabsf(x));
    float r = __fdividef(1.f - t, 1.f + t);
    return copysignf(r, x);
}

__device__ __forceinline__ void sp(__nv_bfloat16* xh, __nv_bfloat16* xl, int idx,
                                   float v0, float v1) {
    __nv_bfloat16 h0 = __float2bfloat16(v0), h1 = __float2bfloat16(v1);
    __nv_bfloat162 hp; hp.x = h0; hp.y = h1;
    *(__nv_bfloat162*)(xh + idx) = hp;
    __nv_bfloat162 lp;
    lp.x = __float2bfloat16(v0 - __bfloat162float(h0));
    lp.y = __float2bfloat16(v1 - __bfloat162float(h1));
    *(__nv_bfloat162*)(xl + idx) = lp;
}

// smem byte offsets (per-CTA 113,152 B -> 2 CTAs/SM)
#define OB_XH  0        // [16][XR] bf16 = 8448
#define OB_XL  8448
#define OB_W1S 16896    // 8 warps x 3 stages x 2 arr x 1024B = 49152
#define OB_W2  66048    // 2 arr x 32 x 512B = 32768 (arr stride 16384)
#define OB_RS  98816    // [4][16][36] f32 = 9216
#define OB_LG  108032   // [16][36] f32 = 2304
#define OB_YB  110336   // [8][64] f32 = 2048
#define OB_B2  112384   // 2 x 32 f32
#define OB_SQ  112640   // 512
#define SMEMB  113152

__global__ void split_w12(const float* __restrict__ W1, const float* __restrict__ W2) {
    const size_t n1 = (size_t)NSt * NL * NL;
    for (size_t i = blockIdx.x * blockDim.x + threadIdx.x; i < n1;
         i += (size_t)gridDim.x * blockDim.x) {
        float x = W1[i];
        __nv_bfloat16 h = __float2bfloat16(x);
        g_w1h[i] = h;
        g_w1l[i] = __float2bfloat16(x - __bfloat162float(h));
    }
    const size_t n2 = (size_t)NSt * NOt * NL;
    for (size_t i = blockIdx.x * blockDim.x + threadIdx.x; i < n2;
         i += (size_t)gridDim.x * blockDim.x) {
        float x = W2[i];
        __nv_bfloat16 h = __float2bfloat16(x);
        g_w2h[i] = h;
        g_w2l[i] = __float2bfloat16(x - __bfloat162float(h));
    }
}

__global__ void __launch_bounds__(THR, 2) lalr_all(
    const float* __restrict__ latent0,
    const float* __restrict__ W1, const float* __restrict__ b1,
    const float* __restrict__ W2, const float* __restrict__ b2,
    const int*   __restrict__ state_seq, const int* __restrict__ out_idx,
    float* __restrict__ out)
{
    extern __shared__ char smc[];
    __nv_bfloat16* xh = (__nv_bfloat16*)(smc + OB_XH);
    __nv_bfloat16* xl = (__nv_bfloat16*)(smc + OB_XL);
    float* rs  = (float*)(smc + OB_RS);
    float* lg  = (float*)(smc + OB_LG);
    float* yb  = (float*)(smc + OB_YB);
    float* b2s = (float*)(smc + OB_B2);
    int*  sseq = (int*)(smc + OB_SQ);

    const int tid = threadIdx.x;
    const int w = tid >> 5, l = tid & 31;
    const int rowbase = blockIdx.x * MT;
    const int gid = l >> 2, tg = l & 3;

    // A fragment (m16k16) lane mapping — proven idiom
    const int arow = l & 15;
    const int akof = (l >> 4) * 8;
    // B fragment lane mapping — proven idiom
    const int bn = ((l >> 4) & 1) * 8 + (l & 7);
    const int bk = (l >> 3) & 1;
    // GEMM1 B read offsets in packed+swizzled stage (warp owns 32 cols)
    const int c0b = bn, c1b = 16 + bn;
    const u32 bo0 = (u32)((c0b * 32 + bk * 16) ^ (((c0b >> 2) & 1) << 4));
    const u32 bo1 = (u32)((c1b * 32 + bk * 16) ^ (((c1b >> 2) & 1) << 4));
    // W1 fill (lane = col l, two 16B halves per array)
    const u32 fil0 = (u32)((l * 32) ^ (((l >> 2) & 1) << 4));
    const u32 fil1 = fil0 ^ 16u;
    const u32 wstage = s2u(smc + OB_W1S + w * 6144);  // 3 stages x 2048B
    // W2 fill mapping: o row, k segment of 32 elems (64B)
    const int o2 = tid & 31, kseg = tid >> 5;
    const u32 w2sw = (u32)((o2 & 7) << 4);
    const u32 w2wr = (u32)(o2 * 512 + kseg * 64);
    // GEMM2 warp roles: nh = n16 half, kg = k64 group
    const int nh = w & 1, kg = w >> 1;
    const int orow = nh * 16 + bn;
    // FIXED addressing: swizzle applied to the FULL k-byte offset, row base added after
    const u32 g2row = (u32)(orow * 512);
    const u32 g2sw  = (u32)((orow & 7) << 4);
    const u32 g2kfx = (u32)(kg * 128 + bk * 16);   // bits 4,7+ only (bits 5-6 free for kc)

    // ---- init ----
    if (tid < Tst) sseq[tid] = state_seq[tid];
    {
        int r = tid >> 4, kc = (tid & 15) * 16;
        const float* src = latent0 + (size_t)(rowbase + r) * NL + kc;
        #pragma unroll
        for (int j = 0; j < 16; j += 2)
            sp(xh + r * XR + kc, xl + r * XR + kc, j, src[j], src[j + 1]);
    }
    __syncthreads();

    // W1 chunk issuer (stage passed explicitly; rolling mod-3 counters)
    auto issue_w1 = [&](int ig, size_t rowb, int stg) {
        if (ig < Tst * NCH) {
            size_t off = rowb + ((size_t)(ig & 15) << 4);
            u32 d = wstage + (u32)stg * 2048u;
            cpa16(d + fil0, g_w1h + off);
            cpa16(d + fil1, g_w1h + off + 8);
            cpa16(d + 1024 + fil0, g_w1l + off);
            cpa16(d + 1024 + fil1, g_w1l + off + 8);
        }
        CPA_COMMIT();
    };

    int s = sseq[0];
    size_t w1rb_cur = ((size_t)s * NL + w * 32 + l) * NL;
    issue_w1(0, w1rb_cur, 0);
    issue_w1(1, w1rb_cur, 1);
    int stw = 2;   // next issue stage (mod 3, persistent)
    int str = 0;   // next read stage (mod 3, persistent)

    // ---- W2 prefetch for t=0 ----
    const __nv_bfloat16* w2hp = g_w2h + ((size_t)s * NOt + o2) * NL + kseg * 32;
    const __nv_bfloat16* w2lp = g_w2l + ((size_t)s * NOt + o2) * NL + kseg * 32;
    uint4 qh[4], ql[4];
    #pragma unroll
    for (int i = 0; i < 4; i++) { qh[i] = ((const uint4*)w2hp)[i]; ql[i] = ((const uint4*)w2lp)[i]; }
    float b2r = (tid < NOt) ? b2[s * NOt + tid] : 0.f;

    for (int t = 0; t < Tst; t++) {
        float2 bias[4];
        #pragma unroll
        for (int nb = 0; nb < 4; nb++)
            bias[nb] = *(const float2*)(b1 + s * NL + w * 32 + nb * 8 + 2 * tg);
        int idxv = out_idx[s * NOt + l];
        const int s_nxt = sseq[(t + 1) & (Tst - 1)];
        const size_t w1rb_nxt = ((size_t)s_nxt * NL + w * 32 + l) * NL;

        // W2 -> packed+swizzled smem (prev GEMM2 reads gated by barrier C of t-1)
        {
            char* base = smc + OB_W2;
            #pragma unroll
            for (int i = 0; i < 4; i++) {
                *(uint4*)(base + ((w2wr + i * 16) ^ w2sw)) = qh[i];
                *(uint4*)(base + 16384 + ((w2wr + i * 16) ^ w2sw)) = ql[i];
            }
        }
        if (tid < NOt) b2s[(t & 1) * 32 + tid] = b2r;
        __syncwarp();

        // ---- GEMM1: 3-term bf16 split MMA; warp = m16 x n32 x k256 ----
        float acc[4][4];
        #pragma unroll
        for (int nb = 0; nb < 4; nb++)
            #pragma unroll
            for (int q = 0; q < 4; q++) acc[nb][q] = 0.f;

        const u32 aHb = s2u(xh + arow * XR + akof);
        const u32 aLb = s2u(xl + arow * XR + akof);

        for (int kt = 0; kt < NCH; kt++) {
            const int g = t * NCH + kt;
            CPA_WAIT1();
            __syncwarp();
            const u32 ka = (u32)(kt * 32);
            u32 ah[4], al[4], bh0[4], bh1[4], bl0[4], bl1[4];
            ldsm4(ah, aHb + ka);
            ldsm4(al, aLb + ka);
            const u32 wb = wstage + (u32)str * 2048u;
            ldsm4(bh0, wb + bo0);
            ldsm4(bh1, wb + bo1);
            ldsm4(bl0, wb + 1024 + bo0);
            ldsm4(bl1, wb + 1024 + bo1);
            issue_w1(g + 2, (kt + 2 < NCH) ? w1rb_cur : w1rb_nxt, stw);
            stw = (stw == 2) ? 0 : stw + 1;
            str = (str == 2) ? 0 : str + 1;

            mma16(acc[0], ah, bh0[0], bh0[1]); mma16(acc[1], ah, bh0[2], bh0[3]);
            mma16(acc[2], ah, bh1[0], bh1[1]); mma16(acc[3], ah, bh1[2], bh1[3]);
            mma16(acc[0], ah, bl0[0], bl0[1]); mma16(acc[1], ah, bl0[2], bl0[3]);
            mma16(acc[2], ah, bl1[0], bl1[1]); mma16(acc[3], ah, bl1[2], bl1[3]);
            mma16(acc[0], al, bh0[0], bh0[1]); mma16(acc[1], al, bh0[2], bh0[3]);
            mma16(acc[2], al, bh1[0], bh1[1]); mma16(acc[3], al, bh1[2], bh1[3]);
        }

        // ---- tail prefetch for t+1 ----
        w2hp = g_w2h + ((size_t)s_nxt * NOt + o2) * NL + kseg * 32;
        w2lp = g_w2l + ((size_t)s_nxt * NOt + o2) * NL + kseg * 32;
        #pragma unroll
        for (int i = 0; i < 4; i++) { qh[i] = ((const uint4*)w2hp)[i]; ql[i] = ((const uint4*)w2lp)[i]; }
        b2r = (tid < NOt) ? b2[s_nxt * NOt + tid] : 0.f;
        s = s_nxt;
        w1rb_cur = w1rb_nxt;

        __syncthreads();   // A: all GEMM1 x reads done (single x buffer)

        // ---- epilogue: fast tanh + bf16 split -> x (in place) ----
        #pragma unroll
        for (int nb = 0; nb < 4; nb++) {
            float2 bb = bias[nb];
            float* c = acc[nb];
            int cp = w * 32 + nb * 8 + 2 * tg;
            sp(xh, xl, gid * XR + cp, ftanh(c[0] + bb.x), ftanh(c[1] + bb.y));
            sp(xh, xl, (gid + 8) * XR + cp, ftanh(c[2] + bb.x), ftanh(c[3] + bb.y));
        }
        __syncthreads();   // B: x_{t+1} + w2/b2 smem ready

        // ---- GEMM2 via MMA: warp = m16 x n16(nh) x k64(kg), 3-term ----
        {
            float c2[2][4];
            #pragma unroll
            for (int j = 0; j < 2; j++)
                #pragma unroll
                for (int q = 0; q < 4; q++) c2[j][q] = 0.f;

            const u32 a2h = s2u(xh + arow * XR + kg * 64 + akof);
            const u32 a2l = s2u(xl + arow * XR + kg * 64 + akof);
            const u32 b2b = s2u(smc + OB_W2);

            #pragma unroll
            for (int kc = 0; kc < 4; kc++) {
                const u32 kb = (u32)(kc * 32);
                // FIXED: swizzle the full k-offset, then add row base (no carry past swizzle)
                const u32 boff = g2row + ((g2kfx | kb) ^ g2sw);
                u32 ah[4], al[4], bh[4], bl[4];
                ldsm4(ah, a2h + kb);
                ldsm4(al, a2l + kb);
                ldsm4(bh, b2b + boff);
                ldsm4(bl, b2b + 16384 + boff);
                mma16(c2[0], ah, bh[0], bh[1]); mma16(c2[1], ah, bh[2], bh[3]);
                mma16(c2[0], ah, bl[0], bl[1]); mma16(c2[1], ah, bl[2], bl[3]);
                mma16(c2[0], al, bh[0], bh[1]); mma16(c2[1], al, bh[2], bh[3]);
            }
            #pragma unroll
            for (int j = 0; j < 2; j++) {
                float* dst = rs + (kg * 16 + gid) * 36 + nh * 16 + j * 8 + 2 * tg;
                float2 lo; lo.x = c2[j][0]; lo.y = c2[j][1];
                float2 hi; hi.x = c2[j][2]; hi.y = c2[j][3];
                *(float2*)dst = lo;
                *(float2*)(dst + 8 * 36) = hi;
            }
        }
        __syncthreads();   // C: partials ready

        // ---- split-k reduce -> logits (warp-local rows) ----
        {
            int rrow = tid >> 4;            // == 2w + (l>>4)
            int cc = (tid & 15) * 2;
            const float* bb = b2s + (t & 1) * 32;
            float2 sum; sum.x = bb[cc]; sum.y = bb[cc + 1];
            #pragma unroll
            for (int kg2 = 0; kg2 < 4; kg2++) {
                float2 v = *(const float2*)(rs + (kg2 * 16 + rrow) * 36 + cc);
                sum.x += v.x; sum.y += v.y;
            }
            *(float2*)(lg + rrow * SLG + cc) = sum;
        }
        __syncwarp();

        // ---- softmax + last-write-wins scatter + out ----
        {
            float* y = yb + w * 64;
            unsigned mset = __match_any_sync(0xffffffffu, idxv);
            bool leader = (31 - __clz(mset)) == l;
            #pragma unroll
            for (int rr = 0; rr < 2; rr++) {
                int row = w * 2 + rr;
                float v = lg[row * SLG + l];
                float m = v;
                #pragma unroll
                for (int off = 16; off > 0; off >>= 1)
                    m = fmaxf(m, __shfl_xor_sync(0xffffffffu, m, off));
                float e = __expf(v - m);
                float ssum = e;
                #pragma unroll
                for (int off = 16; off > 0; off >>= 1)
                    ssum += __shfl_xor_sync(0xffffffffu, ssum, off);
                float p = e / ssum;
                y[l] = 0.f; y[l + 32] = 0.f;
                __syncwarp();
                if (leader) y[idxv] = p;
                __syncwarp();
                float* op = out + (size_t)(rowbase + row) * (Tst * Vt) + (size_t)t * Vt;
                *(float2*)(op + 2 * l) = *(const float2*)(y + 2 * l);
                __syncwarp();
            }
        }
    }
}

extern "C" void kernel_launch(void* const* d_in, const int* in_sizes, int n_in,
                              void* d_out, int out_size)
{
    const float* latent0   = (const float*)d_in[0];
    const float* W1        = (const float*)d_in[1];
    const float* b1        = (const float*)d_in[2];
    const float* W2        = (const float*)d_in[3];
    const float* b2        = (const float*)d_in[4];
    const int*   state_seq = (const int*)  d_in[5];
    const int*   out_idx   = (const int*)  d_in[6];
    float* out = (float*)d_out;

    split_w12<<<2048, 512>>>(W1, W2);

    cudaFuncSetAttribute(lalr_all, cudaFuncAttributeMaxDynamicSharedMemorySize, SMEMB);
    lalr_all<<<Bsz / MT, THR, SMEMB>>>(
        latent0, W1, b1, W2, b2, state_seq, out_idx, out);
}

// round 14
// speedup vs baseline: 2.5700x; 2.5700x over previous
#include <cuda_runtime.h>
#include <cuda_bf16.h>
#include <cstdint>

#define Bsz 4096
#define Tst 128
#define NL  256
#define NSt 64
#define NOt 32
#define Vt  64
#define MT  32
#define XR  264        // x row stride (bf16)
#define NCH 16
#define SLG 36
#define W2R 264        // w2 smem row stride (bf16)

typedef unsigned long long ull;
typedef uint32_t u32;

__device__ __nv_bfloat16 g_w1h[(size_t)NSt * NL * NL];
__device__ __nv_bfloat16 g_w1l[(size_t)NSt * NL * NL];
__device__ __nv_bfloat16 g_w2h[(size_t)NSt * NOt * NL];
__device__ __nv_bfloat16 g_w2l[(size_t)NSt * NOt * NL];

__device__ __forceinline__ u32 s2u(const void* p) {
    return (u32)__cvta_generic_to_shared(p);
}
__device__ __forceinline__ void ldsm4(u32* r, u32 a) {
    asm volatile("ldmatrix.sync.aligned.m8n8.x4.shared.b16 {%0,%1,%2,%3}, [%4];"
        : "=r"(r[0]), "=r"(r[1]), "=r"(r[2]), "=r"(r[3]) : "r"(a));
}
__device__ __forceinline__ void mma16(float* c, const u32* a, u32 b0, u32 b1) {
    asm volatile("mma.sync.aligned.m16n8k16.row.col.f32.bf16.bf16.f32 "
        "{%0,%1,%2,%3},{%4,%5,%6,%7},{%8,%9},{%0,%1,%2,%3};"
        : "+f"(c[0]), "+f"(c[1]), "+f"(c[2]), "+f"(c[3])
        : "r"(a[0]), "r"(a[1]), "r"(a[2]), "r"(a[3]), "r"(b0), "r"(b1));
}
__device__ __forceinline__ void cpa16(u32 dst, const void* src) {
    asm volatile("cp.async.cg.shared.global [%0], [%1], 16;"
        :: "r"(dst), "l"(src) : "memory");
}
#define CPA_COMMIT() asm volatile("cp.async.commit_group;" ::: "memory")
#define CPA_WAIT4()  asm volatile("cp.async.wait_group 4;" ::: "memory")

// Fast branch-free tanh: |abs err| <~ 2^-21, no overflow.
__device__ __forceinline__ float ftanh(float x) {
    float t = __expf(-2.f * fabsf(x));
    float r = __fdividef(1.f - t, 1.f + t);
    return copysignf(r, x);
}

__device__ __forceinline__ void sp(__nv_bfloat16* xh, __nv_bfloat16* xl, int idx,
                                   float v0, float v1) {
    __nv_bfloat16 h0 = __float2bfloat16(v0), h1 = __float2bfloat16(v1);
    __nv_bfloat162 hp; hp.x = h0; hp.y = h1;
    *(__nv_bfloat162*)(xh + idx) = hp;
    __nv_bfloat162 lp;
    lp.x = __float2bfloat16(v0 - __bfloat162float(h0));
    lp.y = __float2bfloat16(v1 - __bfloat162float(h1));
    *(__nv_bfloat162*)(xl + idx) = lp;
}

// smem byte offsets (identical budget to R10)
#define OB_XH0 0                 // [32][XR] bf16  16896
#define OB_XL0 16896
#define OB_XH1 33792             // second x buffer
#define OB_XL1 50688
#define OB_W1S 67584             // 16 warps x 6 stages x (512 hi + 512 lo) = 98304
#define OB_W2H 165888            // 16896
#define OB_W2L 182784            // 16896
#define OB_RS  199680            // [4][32][36] f32 = 18432
#define OB_LG  218112            // 4608
#define OB_YB  222720            // 4096
#define OB_B2  226816            // 2 x 32 f32 (double-buffered)
#define OB_SQ  227072            // 512
#define SMEMB  227584

__global__ void split_w12(const float* __restrict__ W1, const float* __restrict__ W2) {
    const size_t n1 = (size_t)NSt * NL * NL;
    for (size_t i = blockIdx.x * blockDim.x + threadIdx.x; i < n1;
         i += (size_t)gridDim.x * blockDim.x) {
        float x = W1[i];
        __nv_bfloat16 h = __float2bfloat16(x);
        g_w1h[i] = h;
        g_w1l[i] = __float2bfloat16(x - __bfloat162float(h));
    }
    const size_t n2 = (size_t)NSt * NOt * NL;
    for (size_t i = blockIdx.x * blockDim.x + threadIdx.x; i < n2;
         i += (size_t)gridDim.x * blockDim.x) {
        float x = W2[i];
        __nv_bfloat16 h = __float2bfloat16(x);
        g_w2h[i] = h;
        g_w2l[i] = __float2bfloat16(x - __bfloat162float(h));
    }
}

__global__ void __launch_bounds__(512, 1) lalr_all(
    const float* __restrict__ latent0,
    const float* __restrict__ W1, const float* __restrict__ b1,
    const float* __restrict__ W2, const float* __restrict__ b2,
    const int*   __restrict__ state_seq, const int* __restrict__ out_idx,
    float* __restrict__ out)
{
    extern __shared__ char smc[];
    float* rs  = (float*)(smc + OB_RS);
    float* lg  = (float*)(smc + OB_LG);
    float* yb  = (float*)(smc + OB_YB);
    float* b2s = (float*)(smc + OB_B2);
    int*  sseq = (int*)(smc + OB_SQ);

    const int tid = threadIdx.x;
    const int w = tid >> 5, l = tid & 31;
    const int rowbase = blockIdx.x * MT;
    const int gid = l >> 2, tg = l & 3;

    // A fragment lane mapping — proven idiom
    const int arow = l & 15;
    const int akof = (l >> 4) * 8;
    // B fragment lane mapping — proven idiom
    const int bn = ((l >> 4) & 1) * 8 + (l & 7);
    const int bk = (l >> 3) & 1;
    // GEMM1 B read offset in packed+swizzled stage (warp owns 16 cols, 512B/arr)
    const u32 bo = (u32)((bn * 32 + bk * 16) ^ (((bn >> 2) & 1) << 4));
    // W1 cp.async fill mapping: lane -> col fn, k-half (l>>4)
    const int fn = l & 15;
    const u32 fil = (u32)((fn * 32 + (l >> 4) * 16) ^ (((fn >> 2) & 1) << 4));
    const u32 wstage = s2u(smc + OB_W1S + w * 6144);   // 6 stages x 1024B
    // W2 fill / GEMM2 mappings (unchanged from R10)
    const int bofs264 = (bn * W2R + bk * 8) * 2;
    const int o2 = tid & 31, kq2 = (tid >> 5) * 16;
    const int mi2 = w & 1, nh = (w >> 1) & 1, kg = w >> 2;

    // ---- init ----
    if (tid < Tst) sseq[tid] = state_seq[tid];
    {
        __nv_bfloat16* xh0 = (__nv_bfloat16*)(smc + OB_XH0);
        __nv_bfloat16* xl0 = (__nv_bfloat16*)(smc + OB_XL0);
        int r = tid >> 4, kc = (tid & 15) * 16;
        const float* src = latent0 + (size_t)(rowbase + r) * NL + kc;
        #pragma unroll
        for (int j = 0; j < 16; j += 2)
            sp(xh0 + r * XR + kc, xl0 + r * XR + kc, j, src[j], src[j + 1]);
    }
    __syncthreads();

    // W1 chunk issuer: explicit stage, packed 512B layout
    auto issue_w1 = [&](int ig, size_t base, int stg) {
        if (ig < Tst * NCH) {
            size_t off = base + ((size_t)(ig & 15) << 4);
            u32 d = wstage + (u32)stg * 1024u;
            cpa16(d + fil, g_w1h + off);
            cpa16(d + 512 + fil, g_w1l + off);
        }
        CPA_COMMIT();
    };

    // ---- prologue: issue chunks 0..4 (stages 0..4) ----
    int s = sseq[0];
    size_t base_cur = ((size_t)s * NL + w * 16 + fn) * NL + (l >> 4) * 8;
    issue_w1(0, base_cur, 0);
    issue_w1(1, base_cur, 1);
    issue_w1(2, base_cur, 2);
    issue_w1(3, base_cur, 3);
    issue_w1(4, base_cur, 4);
    int istg = 5, rstg = 0;

    const __nv_bfloat16* w2hsrc = g_w2h + ((size_t)s * NOt + o2) * NL + kq2;
    const __nv_bfloat16* w2lsrc = g_w2l + ((size_t)s * NOt + o2) * NL + kq2;
    uint4 qh0 = *(const uint4*)(w2hsrc);
    uint4 qh1 = *(const uint4*)(w2hsrc + 8);
    uint4 ql0 = *(const uint4*)(w2lsrc);
    uint4 ql1 = *(const uint4*)(w2lsrc + 8);
    float b2r = (tid < NOt) ? b2[s * NOt + tid] : 0.f;

    for (int t = 0; t < Tst; t++) {
        char* xcb = smc + (t & 1) * 33792;
        char* xnb = smc + ((t & 1) ^ 1) * 33792;
        __nv_bfloat16* xh_c = (__nv_bfloat16*)(xcb + OB_XH0);
        __nv_bfloat16* xl_c = (__nv_bfloat16*)(xcb + OB_XL0);
        __nv_bfloat16* xh_n = (__nv_bfloat16*)(xnb + OB_XH0);
        __nv_bfloat16* xl_n = (__nv_bfloat16*)(xnb + OB_XL0);

        float2 bias0 = *(const float2*)(b1 + s * NL + w * 16 + 2 * tg);
        float2 bias1 = *(const float2*)(b1 + s * NL + w * 16 + 8 + 2 * tg);
        int idxv = out_idx[s * NOt + l];
        const int s_nxt = sseq[(t + 1) & (Tst - 1)];
        const size_t base_nxt = ((size_t)s_nxt * NL + w * 16 + fn) * NL + (l >> 4) * 8;

        // W2 -> smem [o][W2R] bf16 h/l; b2 -> double-buffered smem
        {
            char* dh = smc + OB_W2H + (o2 * W2R + kq2) * 2;
            char* dl = smc + OB_W2L + (o2 * W2R + kq2) * 2;
            *(uint4*)(dh) = qh0; *(uint4*)(dh + 16) = qh1;
            *(uint4*)(dl) = ql0; *(uint4*)(dl + 16) = ql1;
        }
        if (tid < NOt) b2s[(t & 1) * 32 + tid] = b2r;
        __syncwarp();

        // ---- GEMM1: 3-term bf16 split MMA, fragment-double-buffered ----
        float acc[2][2][4];
        #pragma unroll
        for (int mi = 0; mi < 2; mi++)
            #pragma unroll
            for (int ni = 0; ni < 2; ni++)
                #pragma unroll
                for (int j = 0; j < 4; j++) acc[mi][ni][j] = 0.f;

        const u32 aHb = s2u(xh_c + arow * XR + akof);
        const u32 aLb = s2u(xl_c + arow * XR + akof);

        u32 AH0[2][4], AH1[2][4], AL0[2][4], AL1[2][4], BH[2][4], BL[2][4];

        // preload chunk 0 of this step
        CPA_WAIT4();
        __syncwarp();
        {
            u32 wb = wstage + (u32)rstg * 1024u;
            rstg = (rstg == 5) ? 0 : rstg + 1;
            ldsm4(BH[0], wb + bo);
            ldsm4(BL[0], wb + 512 + bo);
            ldsm4(AH0[0], aHb);
            ldsm4(AH1[0], aHb + 16 * XR * 2);
            ldsm4(AL0[0], aLb);
            ldsm4(AL1[0], aLb + 16 * XR * 2);
        }

        #pragma unroll
        for (int kt = 0; kt < NCH; kt++) {
            const int cur = kt & 1, nxt = cur ^ 1;
            // keep 5 chunks in flight
            issue_w1(t * NCH + kt + 5, (kt + 5 < NCH) ? base_cur : base_nxt, istg);
            istg = (istg == 5) ? 0 : istg + 1;
            if (kt + 1 < NCH) {
                CPA_WAIT4();
                __syncwarp();
                const u32 ka = (u32)((kt + 1) * 32);
                u32 wb = wstage + (u32)rstg * 1024u;
                rstg = (rstg == 5) ? 0 : rstg + 1;
                ldsm4(BH[nxt], wb + bo);
                ldsm4(BL[nxt], wb + 512 + bo);
                ldsm4(AH0[nxt], aHb + ka);
                ldsm4(AH1[nxt], aHb + ka + 16 * XR * 2);
                ldsm4(AL0[nxt], aLb + ka);
                ldsm4(AL1[nxt], aLb + ka + 16 * XR * 2);
            }
            const u32 *ah0 = AH0[cur], *ah1 = AH1[cur];
            const u32 *al0 = AL0[cur], *al1 = AL1[cur];
            const u32 *bh = BH[cur], *bl = BL[cur];
            mma16(acc[0][0], ah0, bh[0], bh[1]); mma16(acc[0][1], ah0, bh[2], bh[3]);
            mma16(acc[1][0], ah1, bh[0], bh[1]); mma16(acc[1][1], ah1, bh[2], bh[3]);
            mma16(acc[0][0], ah0, bl[0], bl[1]); mma16(acc[0][1], ah0, bl[2], bl[3]);
            mma16(acc[1][0], ah1, bl[0], bl[1]); mma16(acc[1][1], ah1, bl[2], bl[3]);
            mma16(acc[0][0], al0, bh[0], bh[1]); mma16(acc[0][1], al0, bh[2], bh[3]);
            mma16(acc[1][0], al1, bh[0], bh[1]); mma16(acc[1][1], al1, bh[2], bh[3]);
        }

        // ---- tail prefetch for t+1 (W2 h/l + b2) ----
        w2hsrc = g_w2h + ((size_t)s_nxt * NOt + o2) * NL + kq2;
        w2lsrc = g_w2l + ((size_t)s_nxt * NOt + o2) * NL + kq2;
        qh0 = *(const uint4*)(w2hsrc);
        qh1 = *(const uint4*)(w2hsrc + 8);
        ql0 = *(const uint4*)(w2lsrc);
        ql1 = *(const uint4*)(w2lsrc + 8);
        b2r = (tid < NOt) ? b2[s_nxt * NOt + tid] : 0.f;
        s = s_nxt;
        base_cur = base_nxt;

        // ---- epilogue: fast tanh + bf16 split -> NEXT x buffer ----
        #pragma unroll
        for (int mi = 0; mi < 2; mi++)
            #pragma unroll
            for (int ni = 0; ni < 2; ni++) {
                float2 bias = ni ? bias1 : bias0;
                float* c = acc[mi][ni];
                int cp = w * 16 + ni * 8 + 2 * tg;
                int r0 = mi * 16 + gid;
                sp(xh_n, xl_n, r0 * XR + cp, ftanh(c[0] + bias.x), ftanh(c[1] + bias.y));
                sp(xh_n, xl_n, (r0 + 8) * XR + cp, ftanh(c[2] + bias.x), ftanh(c[3] + bias.y));
            }
        __syncthreads();   // B: x_{t+1} + w2/b2 smem ready

        // ---- GEMM2 via MMA: warp = m16(mi2) x n16(nh) x k64(kg), 3-term ----
        {
            float c2[2][4];
            #pragma unroll
            for (int j = 0; j < 2; j++)
                #pragma unroll
                for (int q = 0; q < 4; q++) c2[j][q] = 0.f;

            const u32 a2h = s2u(xh_n + (mi2 * 16 + arow) * XR + kg * 64 + akof);
            const u32 a2l = s2u(xl_n + (mi2 * 16 + arow) * XR + kg * 64 + akof);
            const u32 b2hB = s2u(smc + OB_W2H) + nh * 16 * W2R * 2 + bofs264 + kg * 128;
            const u32 b2lB = s2u(smc + OB_W2L) + nh * 16 * W2R * 2 + bofs264 + kg * 128;

            #pragma unroll
            for (int kc = 0; kc < 4; kc++) {
                const u32 kb = (u32)(kc * 32);
                u32 ah[4], al[4], bh[4], bl[4];
                ldsm4(ah, a2h + kb);
                ldsm4(al, a2l + kb);
                ldsm4(bh, b2hB + kb);
                ldsm4(bl, b2lB + kb);
                mma16(c2[0], ah, bh[0], bh[1]); mma16(c2[1], ah, bh[2], bh[3]);
                mma16(c2[0], ah, bl[0], bl[1]); mma16(c2[1], ah, bl[2], bl[3]);
                mma16(c2[0], al, bh[0], bh[1]); mma16(c2[1], al, bh[2], bh[3]);
            }
            #pragma unroll
            for (int j = 0; j < 2; j++) {
                float* dst = rs + (kg * 32 + mi2 * 16 + gid) * 36 + nh * 16 + j * 8 + 2 * tg;
                float2 lo; lo.x = c2[j][0]; lo.y = c2[j][1];
                float2 hi; hi.x = c2[j][2]; hi.y = c2[j][3];
                *(float2*)dst = lo;
                *(float2*)(dst + 8 * 36) = hi;
            }
        }
        __syncthreads();   // C: partials ready

        // ---- split-k reduce -> logits ----
        {
            int rrow = 2 * w + (l >> 4);
            int cc = (l & 15) * 2;
            const float* bb = b2s + (t & 1) * 32;
            float2 sum; sum.x = bb[cc]; sum.y = bb[cc + 1];
            #pragma unroll
            for (int kg2 = 0; kg2 < 4; kg2++) {
                float2 v = *(const float2*)(rs + (kg2 * 32 + rrow) * 36 + cc);
                sum.x += v.x; sum.y += v.y;
            }
            *(float2*)(lg + rrow * SLG + cc) = sum;
        }
        __syncwarp();

        // ---- softmax + last-write-wins scatter + out ----
        {
            float* y = yb + w * 64;
            unsigned mset = __match_any_sync(0xffffffffu, idxv);
            bool leader = (31 - __clz(mset)) == l;
            #pragma unroll
            for (int rr = 0; rr < 2; rr++) {
                int row = w * 2 + rr;
                float v = lg[row * SLG + l];
                float m = v;
                #pragma unroll
                for (int off = 16; off > 0; off >>= 1)
                    m = fmaxf(m, __shfl_xor_sync(0xffffffffu, m, off));
                float e = __expf(v - m);
                float ssum = e;
                #pragma unroll
                for (int off = 16; off > 0; off >>= 1)
                    ssum += __shfl_xor_sync(0xffffffffu, ssum, off);
                float p = e / ssum;
                y[l] = 0.f; y[l + 32] = 0.f;
                __syncwarp();
                if (leader) y[idxv] = p;
                __syncwarp();
                float* op = out + (size_t)(rowbase + row) * (Tst * Vt) + (size_t)t * Vt;
                *(float2*)(op + 2 * l) = *(const float2*)(y + 2 * l);
                __syncwarp();
            }
        }
    }
}

extern "C" void kernel_launch(void* const* d_in, const int* in_sizes, int n_in,
                              void* d_out, int out_size)
{
    const float* latent0   = (const float*)d_in[0];
    const float* W1        = (const float*)d_in[1];
    const float* b1        = (const float*)d_in[2];
    const float* W2        = (const float*)d_in[3];
    const float* b2        = (const float*)d_in[4];
    const int*   state_seq = (const int*)  d_in[5];
    const int*   out_idx   = (const int*)  d_in[6];
    float* out = (float*)d_out;

    split_w12<<<2048, 512>>>(W1, W2);

    cudaFuncSetAttribute(lalr_all, cudaFuncAttributeMaxDynamicSharedMemorySize, SMEMB);
    lalr_all<<<Bsz / MT, 512, SMEMB>>>(
        latent0, W1, b1, W2, b2, state_seq, out_idx, out);
}